// round 16
// baseline (speedup 1.0000x reference)
#include <cuda_runtime.h>
#include <cuda_bf16.h>
#include <cstdint>
#include <math.h>

#define NB 128
#define NT 8
#define ND 2048
#define NR 4
#define NV 512
#define NN 8192   // V*R*R

#define SCALE_Q 512.0f
#define ISCALE (1.0f / 262144.0f)   // 1/(512*512)

// ---------------- scratch (no allocation allowed) ----------------
__device__ unsigned g_xbar8[NB * ND / 4];   // int8-quantized mean, 4/word
__device__ float g_alpha[NB * NR];
__device__ float g_beta[NB * NR];
__device__ float g_part0[NB * NN];          // signed partial (K 0..1023), scaled
__device__ float g_part1[NB * NN];          // signed partial (K 1024..2047), scaled
__device__ float g_loss[NB];
__device__ int g_done_cnt;                  // zero-init; self-resetting

__device__ __forceinline__ unsigned pack4_s8(float x0, float x1, float x2, float x3) {
  int i0 = __float2int_rn(fminf(fmaxf(x0, -127.f), 127.f));
  int i1 = __float2int_rn(fminf(fmaxf(x1, -127.f), 127.f));
  int i2 = __float2int_rn(fminf(fmaxf(x2, -127.f), 127.f));
  int i3 = __float2int_rn(fminf(fmaxf(x3, -127.f), 127.f));
  unsigned lo = __byte_perm((unsigned)i0, (unsigned)i1, 0x0040);
  unsigned hi = __byte_perm((unsigned)i2, (unsigned)i3, 0x0040);
  return __byte_perm(lo, hi, 0x5410);
}

// =================================================================
// Kernel A: xbar = mean_t(input_embs) -> int8 (scale 512),
// alpha/beta = |xbar @ w_{a,b}| in exact fp32.  (R11-proven, ~7us)
// =================================================================
__global__ __launch_bounds__(512) void prep_kernel(
    const float* __restrict__ x, const float* __restrict__ wa,
    const float* __restrict__ wb) {
  const int b = blockIdx.x;
  const int tid = threadIdx.x;
  const int lane = tid & 31;
  const int warp = tid >> 5;
  const int d4 = tid * 4;
  const float* xb = x + (size_t)b * NT * ND + d4;

  float4 v[NT];
#pragma unroll
  for (int t = 0; t < NT; t++)
    v[t] = *reinterpret_cast<const float4*>(xb + t * ND);
  float4 s4;
  s4.x = (((v[0].x + v[1].x) + (v[2].x + v[3].x)) +
          ((v[4].x + v[5].x) + (v[6].x + v[7].x))) * 0.125f;
  s4.y = (((v[0].y + v[1].y) + (v[2].y + v[3].y)) +
          ((v[4].y + v[5].y) + (v[6].y + v[7].y))) * 0.125f;
  s4.z = (((v[0].z + v[1].z) + (v[2].z + v[3].z)) +
          ((v[4].z + v[5].z) + (v[6].z + v[7].z))) * 0.125f;
  s4.w = (((v[0].w + v[1].w) + (v[2].w + v[3].w)) +
          ((v[4].w + v[5].w) + (v[6].w + v[7].w))) * 0.125f;

  g_xbar8[(b * ND + d4) >> 2] =
      pack4_s8(s4.x * SCALE_Q, s4.y * SCALE_Q, s4.z * SCALE_Q, s4.w * SCALE_Q);

  float p[8] = {0.f, 0.f, 0.f, 0.f, 0.f, 0.f, 0.f, 0.f};
#pragma unroll
  for (int q = 0; q < 4; q++) {
    const float sd = (&s4.x)[q];
    float4 a4 = *reinterpret_cast<const float4*>(wa + (d4 + q) * 4);
    float4 b4 = *reinterpret_cast<const float4*>(wb + (d4 + q) * 4);
    p[0] += sd * a4.x; p[1] += sd * a4.y; p[2] += sd * a4.z; p[3] += sd * a4.w;
    p[4] += sd * b4.x; p[5] += sd * b4.y; p[6] += sd * b4.z; p[7] += sd * b4.w;
  }

  __shared__ float sred[16][8];
#pragma unroll
  for (int q = 0; q < 8; q++) {
    float vv = p[q];
#pragma unroll
    for (int o = 16; o; o >>= 1) vv += __shfl_xor_sync(0xFFFFFFFFu, vv, o);
    if (lane == 0) sred[warp][q] = vv;
  }
  __syncthreads();
  if (tid < 8) {
    float s = 0.f;
#pragma unroll
    for (int w = 0; w < 16; w++) s += sred[w][tid];
    s = fabsf(s);
    if (tid < 4) g_alpha[b * 4 + tid] = s;
    else         g_beta[b * 4 + (tid - 4)] = s;
  }
}

// =================================================================
// Kernel B: split-K int8 IMMA GEMM (m16n8k32, s32 acc).
// 256 blocks (128 n-tiles x 2 k-halves), 256 threads, 2 CTAs/SM.
// A: k-major int8 smem (R11-proven swizzle + ldmatrix).
// B: coalesced float4 loads (R14 pattern), in-register 4x4 transpose
//    -> k-contiguous int8 words, n-major smem pitch 84B (STS
//    conflict-free), LDS.32 fragment loads.
// Stores SIGNED scaled partials; abs in finalize after the add.
// =================================================================
__device__ __forceinline__ void ldsm_x4(unsigned& r0, unsigned& r1,
                                        unsigned& r2, unsigned& r3,
                                        unsigned addr) {
  asm volatile("ldmatrix.sync.aligned.m8n8.x4.shared.b16 {%0,%1,%2,%3}, [%4];"
               : "=r"(r0), "=r"(r1), "=r"(r2), "=r"(r3) : "r"(addr));
}
__device__ __forceinline__ void imma16832(int& c0, int& c1, int& c2, int& c3,
                                          unsigned a0, unsigned a1, unsigned a2,
                                          unsigned a3, unsigned b0, unsigned b1) {
  asm volatile(
      "mma.sync.aligned.m16n8k32.row.col.s32.s8.s8.s32 "
      "{%0,%1,%2,%3}, {%4,%5,%6,%7}, {%8,%9}, {%0,%1,%2,%3};"
      : "+r"(c0), "+r"(c1), "+r"(c2), "+r"(c3)
      : "r"(a0), "r"(a1), "r"(a2), "r"(a3), "r"(b0), "r"(b1));
}
__device__ __forceinline__ unsigned lds_u32(unsigned addr) {
  unsigned v;
  asm volatile("ld.shared.b32 %0, [%1];" : "=r"(v) : "r"(addr));
  return v;
}

#define A_STAGE 8192          // 128 rows x 64 B int8
#define B_PITCH 84            // 64 k-bytes + 20 pad (21 words)
#define B_STAGE (64 * B_PITCH)

__global__ __launch_bounds__(256, 2) void gemm_kernel(const float* __restrict__ wv) {
  __shared__ __align__(16) unsigned char Ash[2 * A_STAGE];
  __shared__ __align__(16) unsigned char Bsh[2 * B_STAGE];

  const int tid = threadIdx.x;
  const int lane = tid & 31;
  const int warp = tid >> 5;
  const int wm = warp & 3;   // M group: rows 32*wm..
  const int wn = warp >> 2;  // N group: cols 32*wn..
  const int bid = blockIdx.x;
  const int kt = bid >> 7;                 // k-half: 0 or 1
  const int n0 = (bid & 127) * 64;
  const int kbase = kt * 1024;             // element k offset
  float* outbuf = kt ? g_part1 : g_part0;

  int acc[2][4][4];
#pragma unroll
  for (int mi = 0; mi < 2; mi++)
#pragma unroll
    for (int g = 0; g < 4; g++)
#pragma unroll
      for (int q = 0; q < 4; q++) acc[mi][g][q] = 0;

  const unsigned aBase = (unsigned)__cvta_generic_to_shared(Ash);
  const unsigned bBase = (unsigned)__cvta_generic_to_shared(Bsh);

  // staging registers
  uint4 aS[2];
  float4 bS[4];
  const int bnb = tid & 15;        // n block: 4 cols starting at 4*bnb
  const int bkb = tid >> 4;        // k word: 4 k-rows starting at 4*bkb

  auto ldg = [&](int it) {
    const int k0 = kbase + it * 64;
    // A: 2 x uint4 (16 int8 k-values each)
#pragma unroll
    for (int i = 0; i < 2; i++) {
      int idx = tid + 256 * i;
      int row = idx >> 2, ch = idx & 3;
      aS[i] = *reinterpret_cast<const uint4*>(
          &g_xbar8[(row * ND + k0) >> 2] + 4 * ch);
    }
    // B: 4 coalesced float4 (4 consecutive k rows, 4 n cols each)
#pragma unroll
    for (int i = 0; i < 4; i++)
      bS[i] = *reinterpret_cast<const float4*>(
          &wv[(size_t)(k0 + 4 * bkb + i) * NN + n0 + 4 * bnb]);
  };

  auto sts = [&](int buf) {
    // A: swizzled 16B chunks (R11-proven)
#pragma unroll
    for (int i = 0; i < 2; i++) {
      int idx = tid + 256 * i;
      int row = idx >> 2, ch = idx & 3;
      int sw = ch ^ ((row >> 1) & 3);
      *reinterpret_cast<uint4*>(&Ash[buf * A_STAGE + row * 64 + 16 * sw]) = aS[i];
    }
    // B: 4x4 in-register transpose -> 4 k-contiguous int8 words,
    //    n-major rows, pitch 84B (STS banks all-distinct)
#pragma unroll
    for (int j = 0; j < 4; j++) {
      unsigned w = pack4_s8((&bS[0].x)[j] * SCALE_Q, (&bS[1].x)[j] * SCALE_Q,
                            (&bS[2].x)[j] * SCALE_Q, (&bS[3].x)[j] * SCALE_Q);
      *reinterpret_cast<unsigned*>(
          &Bsh[buf * B_STAGE + (4 * bnb + j) * B_PITCH + 4 * bkb]) = w;
    }
  };

  auto compute = [&](int buf) {
    const unsigned aB = aBase + buf * A_STAGE;
    const unsigned bB = bBase + buf * B_STAGE;
#pragma unroll
    for (int ks = 0; ks < 2; ks++) {
      // A fragments via ldmatrix x4 (R11-proven mapping)
      unsigned a[2][4];
#pragma unroll
      for (int mi = 0; mi < 2; mi++) {
        int row = wm * 32 + mi * 16 + ((lane >> 3) & 1) * 8 + (lane & 7);
        int ch = 2 * ks + (lane >> 4);
        unsigned addr = aB + row * 64 + 16 * (ch ^ ((row >> 1) & 3));
        ldsm_x4(a[mi][0], a[mi][1], a[mi][2], a[mi][3], addr);
      }
      // B fragments: LDS.32, row n, word (lane&3)+8*ks (+4 for reg1)
      unsigned bf[4][2];
#pragma unroll
      for (int g = 0; g < 4; g++) {
        int nn = wn * 32 + g * 8 + (lane >> 2);
        unsigned base = bB + nn * B_PITCH + 32 * ks + 4 * (lane & 3);
        bf[g][0] = lds_u32(base);
        bf[g][1] = lds_u32(base + 16);
      }
#pragma unroll
      for (int mi = 0; mi < 2; mi++)
#pragma unroll
        for (int g = 0; g < 4; g++)
          imma16832(acc[mi][g][0], acc[mi][g][1], acc[mi][g][2], acc[mi][g][3],
                    a[mi][0], a[mi][1], a[mi][2], a[mi][3],
                    bf[g][0], bf[g][1]);
    }
  };

  ldg(0);
  sts(0);
  __syncthreads();
#pragma unroll 1
  for (int it = 0; it < 16; it++) {
    const int buf = it & 1;
    if (it < 15) ldg(it + 1);           // depth-1 prefetch (proven)
    compute(buf);
    if (it < 15) {
      sts(buf ^ 1);
      __syncthreads();
    }
  }

  // epilogue: scale, store SIGNED partials
#pragma unroll
  for (int mi = 0; mi < 2; mi++) {
    const int m = wm * 32 + mi * 16 + (lane >> 2);
#pragma unroll
    for (int g = 0; g < 4; g++) {
      int n = n0 + wn * 32 + g * 8 + (lane & 3) * 2;
      float v0 = (float)acc[mi][g][0] * ISCALE;
      float v1 = (float)acc[mi][g][1] * ISCALE;
      float v2 = (float)acc[mi][g][2] * ISCALE;
      float v3 = (float)acc[mi][g][3] * ISCALE;
      *reinterpret_cast<float2*>(&outbuf[(size_t)m * NN + n]) = make_float2(v0, v1);
      *reinterpret_cast<float2*>(&outbuf[(size_t)(m + 8) * NN + n]) = make_float2(v2, v3);
    }
  }
}

// =================================================================
// Kernel C: per-batch marg scan (|p0+p1|), label gather, 4x4 chains,
// loss_b, fused last-block mean reduction -> out[0]  (R14-proven)
// =================================================================
__global__ __launch_bounds__(128) void finalize_kernel(
    const int* __restrict__ labels, float* __restrict__ out) {
  const int b = blockIdx.x;
  const int tid = threadIdx.x;
  const float* p0 = g_part0 + (size_t)b * NN;
  const float* p1 = g_part1 + (size_t)b * NN;

  __shared__ float part[8][16];
  __shared__ float marg[16];

  const int ij = tid & 15, vs = tid >> 4;
  const int i = ij >> 2, j = ij & 3;
  float s = 0.f;
  for (int v = vs * 64; v < vs * 64 + 64; v++) {
    int idx = i * (NV * NR) + v * NR + j;
    s += fabsf(p0[idx] + p1[idx]);
  }
  part[vs][ij] = s;
  __syncthreads();
  if (tid < 16) {
    float m = 0.f;
#pragma unroll
    for (int w = 0; w < 8; w++) m += part[w][tid];
    marg[tid] = m;
  }
  __syncthreads();

  if (tid == 0) {
    float res[16], tmp[16], mt[16];
    int lab = labels[b * NT];
#pragma unroll
    for (int q = 0; q < 16; q++) {
      int idx = (q >> 2) * (NV * NR) + lab * NR + (q & 3);
      res[q] = fabsf(p0[idx] + p1[idx]);
    }
    for (int t = 1; t < NT; t++) {
      lab = labels[b * NT + t];
#pragma unroll
      for (int q = 0; q < 16; q++) {
        int idx = (q >> 2) * (NV * NR) + lab * NR + (q & 3);
        mt[q] = fabsf(p0[idx] + p1[idx]);
      }
#pragma unroll
      for (int ii = 0; ii < 4; ii++)
#pragma unroll
        for (int jj = 0; jj < 4; jj++) {
          float acc = 0.f;
#pragma unroll
          for (int kk = 0; kk < 4; kk++) acc += res[ii * 4 + kk] * mt[kk * 4 + jj];
          tmp[ii * 4 + jj] = acc;
        }
#pragma unroll
      for (int q = 0; q < 16; q++) res[q] = tmp[q];
    }
    const float* al = g_alpha + b * 4;
    const float* be = g_beta + b * 4;
    float u = 0.f;
#pragma unroll
    for (int ii = 0; ii < 4; ii++)
#pragma unroll
      for (int jj = 0; jj < 4; jj++) u += al[ii] * res[ii * 4 + jj] * be[jj];

    float zc[16];
#pragma unroll
    for (int q = 0; q < 16; q++) zc[q] = marg[q];
    for (int t = 0; t < NT; t++) {   // zc = marg^(T+1)
#pragma unroll
      for (int ii = 0; ii < 4; ii++)
#pragma unroll
        for (int jj = 0; jj < 4; jj++) {
          float acc = 0.f;
#pragma unroll
          for (int kk = 0; kk < 4; kk++) acc += zc[ii * 4 + kk] * marg[kk * 4 + jj];
          tmp[ii * 4 + jj] = acc;
        }
#pragma unroll
      for (int q = 0; q < 16; q++) zc[q] = tmp[q];
    }
    float z = 0.f;
#pragma unroll
    for (int ii = 0; ii < 4; ii++)
#pragma unroll
      for (int jj = 0; jj < 4; jj++) z += al[ii] * zc[ii * 4 + jj] * be[jj];

    g_loss[b] = logf(z) - logf(u);   // = -log(u/z)
  }

  // ---- fused mean reduction: last block to finish does it ----
  __shared__ int is_last;
  if (tid == 0) {
    __threadfence();
    int prev = atomicAdd(&g_done_cnt, 1);
    is_last = (prev == NB - 1);
  }
  __syncthreads();
  if (is_last) {
    __threadfence();
    float v = g_loss[tid];
#pragma unroll
    for (int o = 16; o; o >>= 1) v += __shfl_xor_sync(0xFFFFFFFFu, v, o);
    __shared__ float sw[4];
    if ((tid & 31) == 0) sw[tid >> 5] = v;
    __syncthreads();
    if (tid == 0) {
      out[0] = (sw[0] + sw[1] + sw[2] + sw[3]) * (1.0f / 128.0f);
      atomicExch(&g_done_cnt, 0);   // reset for next graph replay
    }
  }
}

// =================================================================
extern "C" void kernel_launch(void* const* d_in, const int* in_sizes, int n_in,
                              void* d_out, int out_size) {
  const float* x      = (const float*)d_in[0];   // [128, 8, 2048]
  const int*   labels = (const int*)  d_in[1];   // [128, 8]
  const float* wa     = (const float*)d_in[2];   // [2048, 4]
  const float* wb     = (const float*)d_in[3];   // [2048, 4]
  const float* wv     = (const float*)d_in[4];   // [2048, 8192]
  float* out = (float*)d_out;

  prep_kernel<<<NB, 512>>>(x, wa, wb);
  gemm_kernel<<<2 * (NN / 64), 256>>>(wv);
  finalize_kernel<<<NB, 128>>>(labels, out);
}